// round 1
// baseline (speedup 1.0000x reference)
#include <cuda_runtime.h>
#include <cstdint>

#define N_NODES 30000
#define E_EDGES 480000
#define HID 256
#define HEADS 8
#define OUTC 32
#define L_LAYERS 6
#define NODE_IN 13
#define EDGE_IN 10

// ------------------- static device scratch -------------------
__device__ float g_h[N_NODES * HID];
__device__ float g_xl[N_NODES * HID];
__device__ float g_xr[N_NODES * HID];
__device__ float g_eaA[E_EDGES * HID];
__device__ float g_eaB[E_EDGES * HID];
__device__ float g_ep[E_EDGES * HID];
__device__ float g_logits[E_EDGES * HEADS];
__device__ float g_mx[N_NODES * HEADS];
__device__ float g_den[N_NODES * HEADS];
__device__ float g_h2[N_NODES * (HID / 2)];
__device__ int g_rowptr[N_NODES + 1];
__device__ int g_fill[N_NODES];
__device__ int g_perm[E_EDGES];
__device__ int g_src[E_EDGES];
__device__ int g_dst[E_EDGES];

static inline int cdiv(int a, int b) { return (a + b - 1) / b; }

// ------------------- CSR build -------------------
__global__ void k_zero_fill() {
    int i = blockIdx.x * blockDim.x + threadIdx.x;
    if (i < N_NODES) g_fill[i] = 0;
}

__global__ void k_count(const int* __restrict__ dst) {
    int e = blockIdx.x * blockDim.x + threadIdx.x;
    if (e < E_EDGES) atomicAdd(&g_fill[dst[e]], 1);
}

__global__ void k_scan() {  // single block, 1024 threads
    __shared__ int sh[1024];
    __shared__ int carry;
    int t = threadIdx.x;
    if (t == 0) carry = 0;
    __syncthreads();
    for (int base = 0; base < N_NODES; base += 1024) {
        int cbase = carry;
        int i = base + t;
        int v = (i < N_NODES) ? g_fill[i] : 0;
        sh[t] = v;
        __syncthreads();
        for (int off = 1; off < 1024; off <<= 1) {
            int tmp = (t >= off) ? sh[t - off] : 0;
            __syncthreads();
            sh[t] += tmp;
            __syncthreads();
        }
        if (i < N_NODES) {
            int ex = cbase + sh[t] - v;
            g_rowptr[i] = ex;
            g_fill[i] = ex;
        }
        __syncthreads();
        if (t == 0) carry = cbase + sh[1023];
        __syncthreads();
    }
    if (t == 0) g_rowptr[N_NODES] = carry;
}

__global__ void k_scatter(const int* __restrict__ src, const int* __restrict__ dst) {
    int e = blockIdx.x * blockDim.x + threadIdx.x;
    if (e < E_EDGES) {
        int d = dst[e];
        int pos = atomicAdd(&g_fill[d], 1);
        g_perm[pos] = e;
        g_src[pos] = src[e];
        g_dst[pos] = d;
    }
}

// ------------------- input projections -------------------
__global__ void k_hinit(const float* __restrict__ x, const float* __restrict__ W,
                        const float* __restrict__ b) {
    int n = blockIdx.x;
    int c = threadIdx.x;
    __shared__ float xr_[NODE_IN];
    if (c < NODE_IN) xr_[c] = x[n * NODE_IN + c];
    __syncthreads();
    float a = b[c];
#pragma unroll
    for (int k = 0; k < NODE_IN; k++) a += xr_[k] * W[k * HID + c];
    g_h[(size_t)n * HID + c] = a;
}

__global__ void k_eainit(const float* __restrict__ eattr, const float* __restrict__ W,
                         const float* __restrict__ b) {
    int i = blockIdx.x;
    int c = threadIdx.x;
    __shared__ float ar[EDGE_IN];
    if (c < EDGE_IN) ar[c] = eattr[(size_t)g_perm[i] * EDGE_IN + c];
    __syncthreads();
    float a = b[c];
#pragma unroll
    for (int k = 0; k < EDGE_IN; k++) a += ar[k] * W[k * HID + c];
    g_eaA[(size_t)i * HID + c] = a;
}

// ------------------- generic fp32 GEMM: C = A[M,K] @ B[K,N] (+bias, act) -------------
// 128x128 tile, BK=8, 256 threads, 8x8 per-thread register tile.
__global__ __launch_bounds__(256) void k_gemm(const float* __restrict__ A,
                                              const float* __restrict__ B,
                                              const float* __restrict__ bias,
                                              float* __restrict__ C,
                                              int M, int Nn, int K, int act) {
    __shared__ float As[8][132];
    __shared__ float Bs[8][128];
    int row0 = blockIdx.y * 128, col0 = blockIdx.x * 128;
    int tid = threadIdx.x;
    int tx = tid & 15, ty = tid >> 4;
    float acc[8][8];
#pragma unroll
    for (int i = 0; i < 8; i++)
#pragma unroll
        for (int j = 0; j < 8; j++) acc[i][j] = 0.f;

    int arow = tid >> 1;
    int acol = (tid & 1) * 4;
    int brow = tid >> 5;
    int bcol = (tid & 31) * 4;

    for (int kt = 0; kt < K; kt += 8) {
        float4 av = make_float4(0.f, 0.f, 0.f, 0.f);
        int ar = row0 + arow;
        if (ar < M) av = *(const float4*)(A + (size_t)ar * K + kt + acol);
        As[acol + 0][arow] = av.x;
        As[acol + 1][arow] = av.y;
        As[acol + 2][arow] = av.z;
        As[acol + 3][arow] = av.w;
        float4 bv = *(const float4*)(B + (size_t)(kt + brow) * Nn + col0 + bcol);
        *(float4*)&Bs[brow][bcol] = bv;
        __syncthreads();
#pragma unroll
        for (int kk = 0; kk < 8; kk++) {
            float ra[8], rb[8];
#pragma unroll
            for (int i = 0; i < 8; i++) ra[i] = As[kk][ty * 8 + i];
#pragma unroll
            for (int j = 0; j < 8; j++) rb[j] = Bs[kk][tx * 8 + j];
#pragma unroll
            for (int i = 0; i < 8; i++)
#pragma unroll
                for (int j = 0; j < 8; j++) acc[i][j] += ra[i] * rb[j];
        }
        __syncthreads();
    }
#pragma unroll
    for (int i = 0; i < 8; i++) {
        int r = row0 + ty * 8 + i;
        if (r >= M) break;
#pragma unroll
        for (int j = 0; j < 8; j++) {
            int c = col0 + tx * 8 + j;
            float v = acc[i][j];
            if (bias) v += bias[c];
            if (act == 1) v = v >= 0.f ? v : 0.01f * v;
            C[(size_t)r * Nn + c] = v;
        }
    }
}

// ------------------- per-edge attention logits -------------------
// one warp per (sorted) edge; lane l handles column h*32+l for each head h
__global__ void k_edge_logits(const float* __restrict__ att) {
    int warp = (blockIdx.x * blockDim.x + threadIdx.x) >> 5;
    int lane = threadIdx.x & 31;
    if (warp >= E_EDGES) return;
    int s = g_src[warp];
    int d = g_dst[warp];
    const float* epr = g_ep + (size_t)warp * HID;
    const float* xls = g_xl + (size_t)s * HID;
    const float* xrd = g_xr + (size_t)d * HID;
    float lg[HEADS];
#pragma unroll
    for (int h = 0; h < HEADS; h++) {
        int c = h * 32 + lane;
        float m = xls[c] + xrd[c] + epr[c];
        m = m >= 0.f ? m : 0.2f * m;
        lg[h] = m * att[c];
    }
#pragma unroll
    for (int h = 0; h < HEADS; h++)
#pragma unroll
        for (int off = 16; off; off >>= 1) lg[h] += __shfl_xor_sync(0xffffffffu, lg[h], off);
    if (lane == 0) {
#pragma unroll
        for (int h = 0; h < HEADS; h++) g_logits[(size_t)warp * HEADS + h] = lg[h];
    }
}

// ------------------- per-node softmax stats (max, sum-exp) ------------
__global__ void k_softmax() {
    int node = (blockIdx.x * blockDim.x + threadIdx.x) >> 5;
    int lane = threadIdx.x & 31;
    if (node >= N_NODES) return;
    int s0 = g_rowptr[node], s1 = g_rowptr[node + 1];
    float mh[HEADS];
#pragma unroll
    for (int h = 0; h < HEADS; h++) mh[h] = -1e30f;
    for (int i = s0 + lane; i < s1; i += 32) {
        const float* Lp = g_logits + (size_t)i * HEADS;
#pragma unroll
        for (int h = 0; h < HEADS; h++) mh[h] = fmaxf(mh[h], Lp[h]);
    }
#pragma unroll
    for (int h = 0; h < HEADS; h++)
#pragma unroll
        for (int off = 16; off; off >>= 1)
            mh[h] = fmaxf(mh[h], __shfl_xor_sync(0xffffffffu, mh[h], off));
    float sh[HEADS];
#pragma unroll
    for (int h = 0; h < HEADS; h++) sh[h] = 0.f;
    for (int i = s0 + lane; i < s1; i += 32) {
        const float* Lp = g_logits + (size_t)i * HEADS;
#pragma unroll
        for (int h = 0; h < HEADS; h++) sh[h] += expf(Lp[h] - mh[h]);
    }
#pragma unroll
    for (int h = 0; h < HEADS; h++)
#pragma unroll
        for (int off = 16; off; off >>= 1) sh[h] += __shfl_xor_sync(0xffffffffu, sh[h], off);
    if (lane == 0) {
#pragma unroll
        for (int h = 0; h < HEADS; h++) {
            g_mx[node * HEADS + h] = mh[h];
            g_den[node * HEADS + h] = sh[h];
        }
    }
}

// ------------------- per-node aggregation + BN + leaky + residual ------------
__global__ __launch_bounds__(256) void k_agg(const float* __restrict__ conv_b,
                                             const float* __restrict__ bn_g,
                                             const float* __restrict__ bn_b,
                                             const float* __restrict__ bn_rm,
                                             const float* __restrict__ bn_rv,
                                             int layer) {
    int n = blockIdx.x;
    int t = threadIdx.x;
    int head = t >> 5;
    __shared__ float smx[HEADS], sden[HEADS];
    __shared__ float sal[64 * HEADS];
    __shared__ int ssrc[64];
    if (t < HEADS) {
        smx[t] = g_mx[n * HEADS + t];
        sden[t] = g_den[n * HEADS + t] + 1e-16f;
    }
    int s0 = g_rowptr[n], s1 = g_rowptr[n + 1];
    float acc = 0.f;
    for (int c0 = s0; c0 < s1; c0 += 64) {
        int cnt = min(64, s1 - c0);
        __syncthreads();
        for (int idx = t; idx < cnt * HEADS; idx += 256) {
            int i = idx >> 3, h = idx & 7;
            sal[idx] = expf(g_logits[(size_t)(c0 + i) * HEADS + h] - smx[h]) / sden[h];
        }
        for (int idx = t; idx < cnt; idx += 256) ssrc[idx] = g_src[c0 + idx];
        __syncthreads();
        for (int i = 0; i < cnt; i++)
            acc += sal[i * HEADS + head] * g_xl[(size_t)ssrc[i] * HID + t];
    }
    float v = acc + conv_b[t];
    v = (v - bn_rm[t]) * rsqrtf(bn_rv[t] + 1e-5f) * bn_g[t] + bn_b[t];
    v = v >= 0.f ? v : 0.01f * v;
    if (layer >= 1) v += g_h[(size_t)n * HID + t];
    g_h[(size_t)n * HID + t] = v;
}

// ------------------- output head: out = h2 @ W2 + b2 -------------------
__global__ void k_out(const float* __restrict__ W2, const float* __restrict__ b2,
                      float* __restrict__ out) {
    int n = (blockIdx.x * blockDim.x + threadIdx.x) >> 5;
    int lane = threadIdx.x & 31;
    if (n >= N_NODES) return;
    const float* hr = g_h2 + (size_t)n * 128;
    float a = 0.f;
#pragma unroll
    for (int j = 0; j < 4; j++) a += hr[j * 32 + lane] * W2[j * 32 + lane];
#pragma unroll
    for (int off = 16; off; off >>= 1) a += __shfl_xor_sync(0xffffffffu, a, off);
    if (lane == 0) out[n] = a + b2[0];
}

// ------------------- launcher -------------------
extern "C" void kernel_launch(void* const* d_in, const int* in_sizes, int n_in,
                              void* d_out, int out_size) {
    const float* x        = (const float*)d_in[0];
    const int*   ei       = (const int*)d_in[1];
    const float* eattr    = (const float*)d_in[2];
    const float* node_W   = (const float*)d_in[3];
    const float* node_b   = (const float*)d_in[4];
    const float* edge_W   = (const float*)d_in[5];
    const float* edge_b   = (const float*)d_in[6];
    const float* Wl       = (const float*)d_in[7];
    const float* bl       = (const float*)d_in[8];
    const float* Wr       = (const float*)d_in[9];
    const float* br       = (const float*)d_in[10];
    const float* We       = (const float*)d_in[11];
    const float* att      = (const float*)d_in[12];
    const float* conv_b   = (const float*)d_in[13];
    const float* Weu      = (const float*)d_in[14];
    const float* beu      = (const float*)d_in[15];
    const float* bn_g     = (const float*)d_in[16];
    const float* bn_b     = (const float*)d_in[17];
    const float* bn_rm    = (const float*)d_in[18];
    const float* bn_rv    = (const float*)d_in[19];
    const float* out_W1   = (const float*)d_in[20];
    const float* out_b1   = (const float*)d_in[21];
    const float* out_W2   = (const float*)d_in[22];
    const float* out_b2   = (const float*)d_in[23];
    float* out = (float*)d_out;

    const int* src = ei;
    const int* dst = ei + E_EDGES;

    float *eaA, *eaB, *eaEP, *hPtr, *xlPtr, *xrPtr, *h2Ptr;
    cudaGetSymbolAddress((void**)&eaA, g_eaA);
    cudaGetSymbolAddress((void**)&eaB, g_eaB);
    cudaGetSymbolAddress((void**)&eaEP, g_ep);
    cudaGetSymbolAddress((void**)&hPtr, g_h);
    cudaGetSymbolAddress((void**)&xlPtr, g_xl);
    cudaGetSymbolAddress((void**)&xrPtr, g_xr);
    cudaGetSymbolAddress((void**)&h2Ptr, g_h2);

    // CSR build (deterministic topology; edge order within a node is
    // atomic-scatter order, which only permutes fp-sum association)
    k_zero_fill<<<cdiv(N_NODES, 256), 256>>>();
    k_count<<<cdiv(E_EDGES, 256), 256>>>(dst);
    k_scan<<<1, 1024>>>();
    k_scatter<<<cdiv(E_EDGES, 256), 256>>>(src, dst);

    // input projections (ea is built directly in sorted-edge order)
    k_hinit<<<N_NODES, HID>>>(x, node_W, node_b);
    k_eainit<<<E_EDGES, HID>>>(eattr, edge_W, edge_b);

    float* ea_cur = eaA;
    float* ea_nxt = eaB;

    for (int i = 0; i < L_LAYERS; i++) {
        const float* Wl_i = Wl + (size_t)i * HID * HID;
        const float* Wr_i = Wr + (size_t)i * HID * HID;
        const float* We_i = We + (size_t)i * HID * HID;
        const float* Weu_i = Weu + (size_t)i * HID * HID;

        dim3 gN(cdiv(HID, 128), cdiv(N_NODES, 128));
        dim3 gE(cdiv(HID, 128), cdiv(E_EDGES, 128));

        k_gemm<<<gN, 256>>>(hPtr, Wl_i, bl + i * HID, xlPtr, N_NODES, HID, HID, 0);
        k_gemm<<<gN, 256>>>(hPtr, Wr_i, br + i * HID, xrPtr, N_NODES, HID, HID, 0);
        k_gemm<<<gE, 256>>>(ea_cur, We_i, nullptr, eaEP, E_EDGES, HID, HID, 0);

        k_edge_logits<<<cdiv(E_EDGES * 32, 256), 256>>>(att + i * HEADS * OUTC);
        k_softmax<<<cdiv(N_NODES * 32, 256), 256>>>();
        k_agg<<<N_NODES, 256>>>(conv_b + i * HID, bn_g + i * HID, bn_b + i * HID,
                                bn_rm + i * HID, bn_rv + i * HID, i);

        if (i < L_LAYERS - 1) {  // the last ea update is dead code in the reference
            k_gemm<<<gE, 256>>>(ea_cur, Weu_i, beu + i * HID, ea_nxt, E_EDGES, HID, HID, 0);
            float* tmp = ea_cur; ea_cur = ea_nxt; ea_nxt = tmp;
        }
    }

    // output MLP
    dim3 gO(1, cdiv(N_NODES, 128));
    k_gemm<<<gO, 256>>>(hPtr, out_W1, out_b1, h2Ptr, N_NODES, HID / 2, HID, 1);
    k_out<<<cdiv(N_NODES * 32, 256), 256>>>(out_W2, out_b2, out);
}

// round 2
// speedup vs baseline: 2.8553x; 2.8553x over previous
#include <cuda_runtime.h>
#include <cstdint>

#define N_NODES 30000
#define E_EDGES 480000
#define HID 256
#define HEADS 8
#define OUTC 32
#define L_LAYERS 6
#define NODE_IN 13
#define EDGE_IN 10

// ------------------- static device scratch -------------------
__device__ float g_h[N_NODES * HID];
__device__ float g_xl[N_NODES * HID];
__device__ float g_xr[N_NODES * HID];
__device__ float g_eaA[E_EDGES * HID];
__device__ float g_eaB[E_EDGES * HID];
__device__ float g_logits[E_EDGES * HEADS];
__device__ float g_mx[N_NODES * HEADS];
__device__ float g_den[N_NODES * HEADS];
__device__ float g_h2[N_NODES * (HID / 2)];
__device__ int g_rowptr[N_NODES + 1];
__device__ int g_fill[N_NODES];
__device__ int g_perm[E_EDGES];
__device__ int g_src[E_EDGES];
__device__ int g_dst[E_EDGES];

static inline int cdiv(int a, int b) { return (a + b - 1) / b; }

// ------------------- CSR build -------------------
__global__ void k_zero_fill() {
    int i = blockIdx.x * blockDim.x + threadIdx.x;
    if (i < N_NODES) g_fill[i] = 0;
}

__global__ void k_count(const int* __restrict__ dst) {
    int e = blockIdx.x * blockDim.x + threadIdx.x;
    if (e < E_EDGES) atomicAdd(&g_fill[dst[e]], 1);
}

__global__ void k_scan() {  // single block, 1024 threads
    __shared__ int sh[1024];
    __shared__ int carry;
    int t = threadIdx.x;
    if (t == 0) carry = 0;
    __syncthreads();
    for (int base = 0; base < N_NODES; base += 1024) {
        int cbase = carry;
        int i = base + t;
        int v = (i < N_NODES) ? g_fill[i] : 0;
        sh[t] = v;
        __syncthreads();
        for (int off = 1; off < 1024; off <<= 1) {
            int tmp = (t >= off) ? sh[t - off] : 0;
            __syncthreads();
            sh[t] += tmp;
            __syncthreads();
        }
        if (i < N_NODES) {
            int ex = cbase + sh[t] - v;
            g_rowptr[i] = ex;
            g_fill[i] = ex;
        }
        __syncthreads();
        if (t == 0) carry = cbase + sh[1023];
        __syncthreads();
    }
    if (t == 0) g_rowptr[N_NODES] = carry;
}

__global__ void k_scatter(const int* __restrict__ src, const int* __restrict__ dst) {
    int e = blockIdx.x * blockDim.x + threadIdx.x;
    if (e < E_EDGES) {
        int d = dst[e];
        int pos = atomicAdd(&g_fill[d], 1);
        g_perm[pos] = e;
        g_src[pos] = src[e];
        g_dst[pos] = d;
    }
}

// ------------------- input projections -------------------
__global__ void k_hinit(const float* __restrict__ x, const float* __restrict__ W,
                        const float* __restrict__ b) {
    int n = blockIdx.x;
    int c = threadIdx.x;
    __shared__ float xr_[NODE_IN];
    if (c < NODE_IN) xr_[c] = x[n * NODE_IN + c];
    __syncthreads();
    float a = b[c];
#pragma unroll
    for (int k = 0; k < NODE_IN; k++) a += xr_[k] * W[k * HID + c];
    g_h[(size_t)n * HID + c] = a;
}

__global__ void k_eainit(const float* __restrict__ eattr, const float* __restrict__ W,
                         const float* __restrict__ b) {
    int i = blockIdx.x;
    int c = threadIdx.x;
    __shared__ float ar[EDGE_IN];
    if (c < EDGE_IN) ar[c] = eattr[(size_t)g_perm[i] * EDGE_IN + c];
    __syncthreads();
    float a = b[c];
#pragma unroll
    for (int k = 0; k < EDGE_IN; k++) a += ar[k] * W[k * HID + c];
    g_eaA[(size_t)i * HID + c] = a;
}

// ------------------- tf32 helpers -------------------
__device__ __forceinline__ uint32_t f2tf32(float x) {
    uint32_t r;
    asm("cvt.rna.tf32.f32 %0, %1;" : "=r"(r) : "f"(x));
    return r;
}

__device__ __forceinline__ void mma_tf32(float& c0, float& c1, float& c2, float& c3,
                                         uint32_t a0, uint32_t a1, uint32_t a2, uint32_t a3,
                                         uint32_t b0, uint32_t b1) {
    asm volatile(
        "mma.sync.aligned.m16n8k8.row.col.f32.tf32.tf32.f32 "
        "{%0,%1,%2,%3},{%4,%5,%6,%7},{%8,%9},{%0,%1,%2,%3};\n"
        : "+f"(c0), "+f"(c1), "+f"(c2), "+f"(c3)
        : "r"(a0), "r"(a1), "r"(a2), "r"(a3), "r"(b0), "r"(b1));
}

// ------------------- tensor-core GEMM, 128x128x32 tiles -------------------
// MODE 0: C = A@B (+bias, optional leaky 0.01)
// MODE 1: attention-logit epilogue (GATv2): no C write; per (edge,head):
//         logits[e][h] = sum_c leaky(xl[src][c]+xr[dst][c]+ep[c], 0.2)*att[c]
template <int MODE>
__global__ __launch_bounds__(256, 2) void k_mma(const float* __restrict__ A,
                                                const float* __restrict__ B,
                                                const float* __restrict__ bias,
                                                float* __restrict__ C,
                                                int M, int N, int K, int act,
                                                const float* __restrict__ att) {
    __shared__ uint32_t As[128][36];   // [m][k], stride 36 (bank-clean)
    __shared__ uint32_t Bs[32][136];   // [k][n], stride 136 (bank-clean)

    const int tid = threadIdx.x;
    const int lane = tid & 31;
    const int warp = tid >> 5;
    const int g = lane >> 2;    // groupID 0..7
    const int t4 = lane & 3;    // threadID-in-group 0..3
    const int wm = warp >> 1;   // 0..3 -> 32-row chunk
    const int wn = warp & 1;    // 0..1 -> 64-col chunk
    const int row0 = blockIdx.y * 128;
    const int col0 = blockIdx.x * 128;

    float acc[2][8][4];
#pragma unroll
    for (int mi = 0; mi < 2; mi++)
#pragma unroll
        for (int ni = 0; ni < 8; ni++)
#pragma unroll
            for (int c = 0; c < 4; c++) acc[mi][ni][c] = 0.f;

    for (int kt = 0; kt < K; kt += 32) {
        // load A tile: 128 rows x 32 cols, 1024 float4, 4 per thread
#pragma unroll
        for (int v = 0; v < 4; v++) {
            int f = tid + v * 256;
            int row = f >> 3;
            int c4 = f & 7;
            int r = row0 + row;
            float4 av = make_float4(0.f, 0.f, 0.f, 0.f);
            if (r < M) av = *(const float4*)(A + (size_t)r * K + kt + c4 * 4);
            uint4 u;
            u.x = f2tf32(av.x); u.y = f2tf32(av.y); u.z = f2tf32(av.z); u.w = f2tf32(av.w);
            *(uint4*)&As[row][c4 * 4] = u;
        }
        // load B tile: 32 rows x 128 cols, 1024 float4, 4 per thread
#pragma unroll
        for (int v = 0; v < 4; v++) {
            int f = tid + v * 256;
            int row = f >> 5;
            int c4 = f & 31;
            float4 bv = *(const float4*)(B + (size_t)(kt + row) * N + col0 + c4 * 4);
            uint4 u;
            u.x = f2tf32(bv.x); u.y = f2tf32(bv.y); u.z = f2tf32(bv.z); u.w = f2tf32(bv.w);
            *(uint4*)&Bs[row][c4 * 4] = u;
        }
        __syncthreads();

#pragma unroll
        for (int kk = 0; kk < 4; kk++) {
            int k0 = kk * 8;
            uint32_t a[2][4];
#pragma unroll
            for (int mi = 0; mi < 2; mi++) {
                int mrow = wm * 32 + mi * 16;
                a[mi][0] = As[mrow + g][k0 + t4];
                a[mi][1] = As[mrow + 8 + g][k0 + t4];
                a[mi][2] = As[mrow + g][k0 + t4 + 4];
                a[mi][3] = As[mrow + 8 + g][k0 + t4 + 4];
            }
            uint32_t b[8][2];
#pragma unroll
            for (int ni = 0; ni < 8; ni++) {
                int ncol = wn * 64 + ni * 8;
                b[ni][0] = Bs[k0 + t4][ncol + g];
                b[ni][1] = Bs[k0 + t4 + 4][ncol + g];
            }
#pragma unroll
            for (int mi = 0; mi < 2; mi++)
#pragma unroll
                for (int ni = 0; ni < 8; ni++)
                    mma_tf32(acc[mi][ni][0], acc[mi][ni][1], acc[mi][ni][2], acc[mi][ni][3],
                             a[mi][0], a[mi][1], a[mi][2], a[mi][3], b[ni][0], b[ni][1]);
        }
        __syncthreads();
    }

    if (MODE == 0) {
#pragma unroll
        for (int mi = 0; mi < 2; mi++) {
#pragma unroll
            for (int j = 0; j < 2; j++) {
                int r = row0 + wm * 32 + mi * 16 + j * 8 + g;
                if (r >= M) continue;
#pragma unroll
                for (int ni = 0; ni < 8; ni++) {
                    int c = col0 + wn * 64 + ni * 8 + 2 * t4;
                    float v0 = acc[mi][ni][j * 2 + 0];
                    float v1 = acc[mi][ni][j * 2 + 1];
                    if (bias) { v0 += bias[c]; v1 += bias[c + 1]; }
                    if (act == 1) {
                        v0 = v0 >= 0.f ? v0 : 0.01f * v0;
                        v1 = v1 >= 0.f ? v1 : 0.01f * v1;
                    }
                    *(float2*)(C + (size_t)r * N + c) = make_float2(v0, v1);
                }
            }
        }
    } else {
        // logits epilogue: warp covers 64 cols = 2 complete heads
        float P[2][2][2];
#pragma unroll
        for (int mi = 0; mi < 2; mi++)
#pragma unroll
            for (int j = 0; j < 2; j++)
#pragma unroll
                for (int h = 0; h < 2; h++) P[mi][j][h] = 0.f;

#pragma unroll
        for (int mi = 0; mi < 2; mi++) {
#pragma unroll
            for (int j = 0; j < 2; j++) {
                int r = row0 + wm * 32 + mi * 16 + j * 8 + g;
                if (r >= M) continue;
                int s = g_src[r];
                int d = g_dst[r];
                const float* xls = g_xl + (size_t)s * HID;
                const float* xrd = g_xr + (size_t)d * HID;
#pragma unroll
                for (int ni = 0; ni < 8; ni++) {
                    int h = ni >> 2;
                    int c = col0 + wn * 64 + ni * 8 + 2 * t4;
                    float e0 = acc[mi][ni][j * 2 + 0] + xls[c] + xrd[c];
                    float e1 = acc[mi][ni][j * 2 + 1] + xls[c + 1] + xrd[c + 1];
                    e0 = e0 >= 0.f ? e0 : 0.2f * e0;
                    e1 = e1 >= 0.f ? e1 : 0.2f * e1;
                    P[mi][j][h] += e0 * att[c] + e1 * att[c + 1];
                }
            }
        }
        // reduce across the 4 lanes sharing a row (lane = g*4 + t4)
#pragma unroll
        for (int mi = 0; mi < 2; mi++)
#pragma unroll
            for (int j = 0; j < 2; j++)
#pragma unroll
                for (int h = 0; h < 2; h++) {
                    float v = P[mi][j][h];
                    v += __shfl_xor_sync(0xffffffffu, v, 1);
                    v += __shfl_xor_sync(0xffffffffu, v, 2);
                    P[mi][j][h] = v;
                }
        if (t4 == 0) {
            int hbase = ((col0 + wn * 64) >> 5);
#pragma unroll
            for (int mi = 0; mi < 2; mi++)
#pragma unroll
                for (int j = 0; j < 2; j++) {
                    int r = row0 + wm * 32 + mi * 16 + j * 8 + g;
                    if (r >= M) continue;
#pragma unroll
                    for (int h = 0; h < 2; h++)
                        g_logits[(size_t)r * HEADS + hbase + h] = P[mi][j][h];
                }
        }
    }
}

// ------------------- per-node softmax stats (max, sum-exp) ------------
__global__ void k_softmax() {
    int node = (blockIdx.x * blockDim.x + threadIdx.x) >> 5;
    int lane = threadIdx.x & 31;
    if (node >= N_NODES) return;
    int s0 = g_rowptr[node], s1 = g_rowptr[node + 1];
    float mh[HEADS];
#pragma unroll
    for (int h = 0; h < HEADS; h++) mh[h] = -1e30f;
    for (int i = s0 + lane; i < s1; i += 32) {
        const float* Lp = g_logits + (size_t)i * HEADS;
#pragma unroll
        for (int h = 0; h < HEADS; h++) mh[h] = fmaxf(mh[h], Lp[h]);
    }
#pragma unroll
    for (int h = 0; h < HEADS; h++)
#pragma unroll
        for (int off = 16; off; off >>= 1)
            mh[h] = fmaxf(mh[h], __shfl_xor_sync(0xffffffffu, mh[h], off));
    float sh[HEADS];
#pragma unroll
    for (int h = 0; h < HEADS; h++) sh[h] = 0.f;
    for (int i = s0 + lane; i < s1; i += 32) {
        const float* Lp = g_logits + (size_t)i * HEADS;
#pragma unroll
        for (int h = 0; h < HEADS; h++) sh[h] += expf(Lp[h] - mh[h]);
    }
#pragma unroll
    for (int h = 0; h < HEADS; h++)
#pragma unroll
        for (int off = 16; off; off >>= 1) sh[h] += __shfl_xor_sync(0xffffffffu, sh[h], off);
    if (lane == 0) {
#pragma unroll
        for (int h = 0; h < HEADS; h++) {
            g_mx[node * HEADS + h] = mh[h];
            g_den[node * HEADS + h] = sh[h];
        }
    }
}

// ------------------- per-node aggregation + BN + leaky + residual ------------
__global__ __launch_bounds__(256) void k_agg(const float* __restrict__ conv_b,
                                             const float* __restrict__ bn_g,
                                             const float* __restrict__ bn_b,
                                             const float* __restrict__ bn_rm,
                                             const float* __restrict__ bn_rv,
                                             int layer) {
    int n = blockIdx.x;
    int t = threadIdx.x;
    int head = t >> 5;
    __shared__ float smx[HEADS], sden[HEADS];
    __shared__ float sal[64 * HEADS];
    __shared__ int ssrc[64];
    if (t < HEADS) {
        smx[t] = g_mx[n * HEADS + t];
        sden[t] = g_den[n * HEADS + t] + 1e-16f;
    }
    int s0 = g_rowptr[n], s1 = g_rowptr[n + 1];
    float acc = 0.f;
    for (int c0 = s0; c0 < s1; c0 += 64) {
        int cnt = min(64, s1 - c0);
        __syncthreads();
        for (int idx = t; idx < cnt * HEADS; idx += 256) {
            int i = idx >> 3, h = idx & 7;
            sal[idx] = expf(g_logits[(size_t)(c0 + i) * HEADS + h] - smx[h]) / sden[h];
        }
        for (int idx = t; idx < cnt; idx += 256) ssrc[idx] = g_src[c0 + idx];
        __syncthreads();
        for (int i = 0; i < cnt; i++)
            acc += sal[i * HEADS + head] * g_xl[(size_t)ssrc[i] * HID + t];
    }
    float v = acc + conv_b[t];
    v = (v - bn_rm[t]) * rsqrtf(bn_rv[t] + 1e-5f) * bn_g[t] + bn_b[t];
    v = v >= 0.f ? v : 0.01f * v;
    if (layer >= 1) v += g_h[(size_t)n * HID + t];
    g_h[(size_t)n * HID + t] = v;
}

// ------------------- output head: out = h2 @ W2 + b2 -------------------
__global__ void k_out(const float* __restrict__ W2, const float* __restrict__ b2,
                      float* __restrict__ out) {
    int n = (blockIdx.x * blockDim.x + threadIdx.x) >> 5;
    int lane = threadIdx.x & 31;
    if (n >= N_NODES) return;
    const float* hr = g_h2 + (size_t)n * 128;
    float a = 0.f;
#pragma unroll
    for (int j = 0; j < 4; j++) a += hr[j * 32 + lane] * W2[j * 32 + lane];
#pragma unroll
    for (int off = 16; off; off >>= 1) a += __shfl_xor_sync(0xffffffffu, a, off);
    if (lane == 0) out[n] = a + b2[0];
}

// ------------------- launcher -------------------
extern "C" void kernel_launch(void* const* d_in, const int* in_sizes, int n_in,
                              void* d_out, int out_size) {
    const float* x        = (const float*)d_in[0];
    const int*   ei       = (const int*)d_in[1];
    const float* eattr    = (const float*)d_in[2];
    const float* node_W   = (const float*)d_in[3];
    const float* node_b   = (const float*)d_in[4];
    const float* edge_W   = (const float*)d_in[5];
    const float* edge_b   = (const float*)d_in[6];
    const float* Wl       = (const float*)d_in[7];
    const float* bl       = (const float*)d_in[8];
    const float* Wr       = (const float*)d_in[9];
    const float* br       = (const float*)d_in[10];
    const float* We       = (const float*)d_in[11];
    const float* att      = (const float*)d_in[12];
    const float* conv_b   = (const float*)d_in[13];
    const float* Weu      = (const float*)d_in[14];
    const float* beu      = (const float*)d_in[15];
    const float* bn_g     = (const float*)d_in[16];
    const float* bn_b     = (const float*)d_in[17];
    const float* bn_rm    = (const float*)d_in[18];
    const float* bn_rv    = (const float*)d_in[19];
    const float* out_W1   = (const float*)d_in[20];
    const float* out_b1   = (const float*)d_in[21];
    const float* out_W2   = (const float*)d_in[22];
    const float* out_b2   = (const float*)d_in[23];
    float* out = (float*)d_out;

    const int* src = ei;
    const int* dst = ei + E_EDGES;

    float *eaA, *eaB, *hPtr, *xlPtr, *xrPtr, *h2Ptr;
    cudaGetSymbolAddress((void**)&eaA, g_eaA);
    cudaGetSymbolAddress((void**)&eaB, g_eaB);
    cudaGetSymbolAddress((void**)&hPtr, g_h);
    cudaGetSymbolAddress((void**)&xlPtr, g_xl);
    cudaGetSymbolAddress((void**)&xrPtr, g_xr);
    cudaGetSymbolAddress((void**)&h2Ptr, g_h2);

    // CSR build
    k_zero_fill<<<cdiv(N_NODES, 256), 256>>>();
    k_count<<<cdiv(E_EDGES, 256), 256>>>(dst);
    k_scan<<<1, 1024>>>();
    k_scatter<<<cdiv(E_EDGES, 256), 256>>>(src, dst);

    // input projections (ea built directly in sorted-edge order)
    k_hinit<<<N_NODES, HID>>>(x, node_W, node_b);
    k_eainit<<<E_EDGES, HID>>>(eattr, edge_W, edge_b);

    float* ea_cur = eaA;
    float* ea_nxt = eaB;

    for (int i = 0; i < L_LAYERS; i++) {
        const float* Wl_i = Wl + (size_t)i * HID * HID;
        const float* Wr_i = Wr + (size_t)i * HID * HID;
        const float* We_i = We + (size_t)i * HID * HID;
        const float* Weu_i = Weu + (size_t)i * HID * HID;

        dim3 gN(cdiv(HID, 128), cdiv(N_NODES, 128));
        dim3 gE(cdiv(HID, 128), cdiv(E_EDGES, 128));

        k_mma<0><<<gN, 256>>>(hPtr, Wl_i, bl + i * HID, xlPtr, N_NODES, HID, HID, 0, nullptr);
        k_mma<0><<<gN, 256>>>(hPtr, Wr_i, br + i * HID, xrPtr, N_NODES, HID, HID, 0, nullptr);
        // ea @ We with fused GATv2 logit epilogue (ep never materialized)
        k_mma<1><<<gE, 256>>>(ea_cur, We_i, nullptr, nullptr, E_EDGES, HID, HID, 0,
                              att + (size_t)i * HEADS * OUTC);

        k_softmax<<<cdiv(N_NODES * 32, 256), 256>>>();
        k_agg<<<N_NODES, 256>>>(conv_b + i * HID, bn_g + i * HID, bn_b + i * HID,
                                bn_rm + i * HID, bn_rv + i * HID, i);

        if (i < L_LAYERS - 1) {  // last ea update is dead code in the reference
            k_mma<0><<<gE, 256>>>(ea_cur, Weu_i, beu + i * HID, ea_nxt, E_EDGES, HID, HID, 0, nullptr);
            float* tmp = ea_cur; ea_cur = ea_nxt; ea_nxt = tmp;
        }
    }

    // output MLP
    dim3 gO(1, cdiv(N_NODES, 128));
    k_mma<0><<<gO, 256>>>(hPtr, out_W1, out_b1, h2Ptr, N_NODES, HID / 2, HID, 1, nullptr);
    k_out<<<cdiv(N_NODES * 32, 256), 256>>>(out_W2, out_b2, out);
}

// round 4
// speedup vs baseline: 6.5991x; 2.3111x over previous
#include <cuda_runtime.h>
#include <cstdint>

#define N_NODES 30000
#define E_EDGES 480000
#define HID 256
#define HEADS 8
#define OUTC 32
#define L_LAYERS 6
#define NODE_IN 13
#define EDGE_IN 10

// ------------------- static device scratch -------------------
__device__ float g_h[N_NODES * HID];
__device__ float g_xl[N_NODES * HID];
__device__ float g_xr[N_NODES * HID];
__device__ float g_attrS[E_EDGES * EDGE_IN];   // permuted edge_attr
__device__ float g_logits[E_EDGES * HEADS];
__device__ float g_mx[N_NODES * HEADS];
__device__ float g_den[N_NODES * HEADS];
__device__ float g_h2[N_NODES * (HID / 2)];
__device__ float g_M[2][EDGE_IN * HID];        // composed attr->ea maps (ping-pong)
__device__ float g_cc[2][HID];
__device__ float g_P[L_LAYERS][EDGE_IN * HID]; // composed attr->ep maps
__device__ float g_q[L_LAYERS][HID];
__device__ int g_rowptr[N_NODES + 1];
__device__ int g_fill[N_NODES];
__device__ int g_perm[E_EDGES];
__device__ int g_src[E_EDGES];
__device__ int g_dst[E_EDGES];

static inline int cdiv(int a, int b) { return (a + b - 1) / b; }

// ------------------- CSR build -------------------
__global__ void k_zero_fill() {
    int i = blockIdx.x * blockDim.x + threadIdx.x;
    if (i < N_NODES) g_fill[i] = 0;
}

__global__ void k_count(const int* __restrict__ dst) {
    int e = blockIdx.x * blockDim.x + threadIdx.x;
    if (e < E_EDGES) atomicAdd(&g_fill[dst[e]], 1);
}

__global__ void k_scan() {  // single block, 1024 threads
    __shared__ int sh[1024];
    __shared__ int carry;
    int t = threadIdx.x;
    if (t == 0) carry = 0;
    __syncthreads();
    for (int base = 0; base < N_NODES; base += 1024) {
        int cbase = carry;
        int i = base + t;
        int v = (i < N_NODES) ? g_fill[i] : 0;
        sh[t] = v;
        __syncthreads();
        for (int off = 1; off < 1024; off <<= 1) {
            int tmp = (t >= off) ? sh[t - off] : 0;
            __syncthreads();
            sh[t] += tmp;
            __syncthreads();
        }
        if (i < N_NODES) {
            int ex = cbase + sh[t] - v;
            g_rowptr[i] = ex;
            g_fill[i] = ex;
        }
        __syncthreads();
        if (t == 0) carry = cbase + sh[1023];
        __syncthreads();
    }
    if (t == 0) g_rowptr[N_NODES] = carry;
}

__global__ void k_scatter(const int* __restrict__ src, const int* __restrict__ dst) {
    int e = blockIdx.x * blockDim.x + threadIdx.x;
    if (e < E_EDGES) {
        int d = dst[e];
        int pos = atomicAdd(&g_fill[d], 1);
        g_perm[pos] = e;
        g_src[pos] = src[e];
        g_dst[pos] = d;
    }
}

__global__ void k_permattr(const float* __restrict__ eattr) {
    int i = blockIdx.x * blockDim.x + threadIdx.x;
    if (i < E_EDGES * EDGE_IN) {
        int e = i / EDGE_IN, j = i - e * EDGE_IN;
        g_attrS[i] = eattr[(size_t)g_perm[e] * EDGE_IN + j];
    }
}

// ------------------- node input projection -------------------
__global__ void k_hinit(const float* __restrict__ x, const float* __restrict__ W,
                        const float* __restrict__ b) {
    int n = blockIdx.x;
    int c = threadIdx.x;
    __shared__ float xr_[NODE_IN];
    if (c < NODE_IN) xr_[c] = x[n * NODE_IN + c];
    __syncthreads();
    float a = b[c];
#pragma unroll
    for (int k = 0; k < NODE_IN; k++) a += xr_[k] * W[k * HID + c];
    g_h[(size_t)n * HID + c] = a;
}

// ------------------- linear edge-chain composition (fp32 exact) -------------------
__global__ void k_initM(const float* __restrict__ edge_W, const float* __restrict__ edge_b) {
    int c = threadIdx.x;
#pragma unroll
    for (int r = 0; r < EDGE_IN; r++) g_M[0][r * HID + c] = edge_W[r * HID + c];
    g_cc[0][c] = edge_b[c];
}

// computes P_i = M@We, q_i = c@We; and (if doNext) M' = M@Weu, c' = c@Weu + beu
__global__ void k_compose(const float* __restrict__ We, const float* __restrict__ Weu,
                          const float* __restrict__ beu, int layer, int cur, int doNext) {
    int c = threadIdx.x;  // 256
    __shared__ float sM[EDGE_IN * HID];
    __shared__ float sc[HID];
    for (int t = c; t < EDGE_IN * HID; t += HID) sM[t] = g_M[cur][t];
    sc[c] = g_cc[cur][c];
    __syncthreads();
    float accP[EDGE_IN], accM[EDGE_IN];
    float accq = 0.f, accc = 0.f;
#pragma unroll
    for (int r = 0; r < EDGE_IN; r++) { accP[r] = 0.f; accM[r] = 0.f; }
    for (int k = 0; k < HID; k++) {
        float we = We[k * HID + c];
        float wu = doNext ? Weu[k * HID + c] : 0.f;
        float ck = sc[k];
        accq += ck * we;
        accc += ck * wu;
#pragma unroll
        for (int r = 0; r < EDGE_IN; r++) {
            float m = sM[r * HID + k];
            accP[r] += m * we;
            accM[r] += m * wu;
        }
    }
#pragma unroll
    for (int r = 0; r < EDGE_IN; r++) g_P[layer][r * HID + c] = accP[r];
    g_q[layer][c] = accq;
    if (doNext) {
#pragma unroll
        for (int r = 0; r < EDGE_IN; r++) g_M[1 - cur][r * HID + c] = accM[r];
        g_cc[1 - cur][c] = accc + beu[c];
    }
}

// ------------------- tf32 helpers -------------------
__device__ __forceinline__ uint32_t f2tf32(float x) {
    uint32_t r;
    asm("cvt.rna.tf32.f32 %0, %1;" : "=r"(r) : "f"(x));
    return r;
}

__device__ __forceinline__ void mma_tf32(float& c0, float& c1, float& c2, float& c3,
                                         uint32_t a0, uint32_t a1, uint32_t a2, uint32_t a3,
                                         uint32_t b0, uint32_t b1) {
    asm volatile(
        "mma.sync.aligned.m16n8k8.row.col.f32.tf32.tf32.f32 "
        "{%0,%1,%2,%3},{%4,%5,%6,%7},{%8,%9},{%0,%1,%2,%3};\n"
        : "+f"(c0), "+f"(c1), "+f"(c2), "+f"(c3)
        : "r"(a0), "r"(a1), "r"(a2), "r"(a3), "r"(b0), "r"(b1));
}

// ------------------- tensor-core GEMM, 128x128x32 tiles -------------------
__global__ __launch_bounds__(256, 2) void k_mma(const float* __restrict__ A,
                                                const float* __restrict__ B,
                                                const float* __restrict__ bias,
                                                float* __restrict__ C,
                                                int M, int N, int K, int act) {
    __shared__ uint32_t As[128][36];
    __shared__ uint32_t Bs[32][136];

    const int tid = threadIdx.x;
    const int lane = tid & 31;
    const int warp = tid >> 5;
    const int g = lane >> 2;
    const int t4 = lane & 3;
    const int wm = warp >> 1;
    const int wn = warp & 1;
    const int row0 = blockIdx.y * 128;
    const int col0 = blockIdx.x * 128;

    float acc[2][8][4];
#pragma unroll
    for (int mi = 0; mi < 2; mi++)
#pragma unroll
        for (int ni = 0; ni < 8; ni++)
#pragma unroll
            for (int c = 0; c < 4; c++) acc[mi][ni][c] = 0.f;

    for (int kt = 0; kt < K; kt += 32) {
#pragma unroll
        for (int v = 0; v < 4; v++) {
            int f = tid + v * 256;
            int row = f >> 3;
            int c4 = f & 7;
            int r = row0 + row;
            float4 av = make_float4(0.f, 0.f, 0.f, 0.f);
            if (r < M) av = *(const float4*)(A + (size_t)r * K + kt + c4 * 4);
            uint4 u;
            u.x = f2tf32(av.x); u.y = f2tf32(av.y); u.z = f2tf32(av.z); u.w = f2tf32(av.w);
            *(uint4*)&As[row][c4 * 4] = u;
        }
#pragma unroll
        for (int v = 0; v < 4; v++) {
            int f = tid + v * 256;
            int row = f >> 5;
            int c4 = f & 31;
            float4 bv = *(const float4*)(B + (size_t)(kt + row) * N + col0 + c4 * 4);
            uint4 u;
            u.x = f2tf32(bv.x); u.y = f2tf32(bv.y); u.z = f2tf32(bv.z); u.w = f2tf32(bv.w);
            *(uint4*)&Bs[row][c4 * 4] = u;
        }
        __syncthreads();

#pragma unroll
        for (int kk = 0; kk < 4; kk++) {
            int k0 = kk * 8;
            uint32_t a[2][4];
#pragma unroll
            for (int mi = 0; mi < 2; mi++) {
                int mrow = wm * 32 + mi * 16;
                a[mi][0] = As[mrow + g][k0 + t4];
                a[mi][1] = As[mrow + 8 + g][k0 + t4];
                a[mi][2] = As[mrow + g][k0 + t4 + 4];
                a[mi][3] = As[mrow + 8 + g][k0 + t4 + 4];
            }
            uint32_t b[8][2];
#pragma unroll
            for (int ni = 0; ni < 8; ni++) {
                int ncol = wn * 64 + ni * 8;
                b[ni][0] = Bs[k0 + t4][ncol + g];
                b[ni][1] = Bs[k0 + t4 + 4][ncol + g];
            }
#pragma unroll
            for (int mi = 0; mi < 2; mi++)
#pragma unroll
                for (int ni = 0; ni < 8; ni++)
                    mma_tf32(acc[mi][ni][0], acc[mi][ni][1], acc[mi][ni][2], acc[mi][ni][3],
                             a[mi][0], a[mi][1], a[mi][2], a[mi][3], b[ni][0], b[ni][1]);
        }
        __syncthreads();
    }

#pragma unroll
    for (int mi = 0; mi < 2; mi++) {
#pragma unroll
        for (int j = 0; j < 2; j++) {
            int r = row0 + wm * 32 + mi * 16 + j * 8 + g;
            if (r >= M) continue;
#pragma unroll
            for (int ni = 0; ni < 8; ni++) {
                int c = col0 + wn * 64 + ni * 8 + 2 * t4;
                float v0 = acc[mi][ni][j * 2 + 0];
                float v1 = acc[mi][ni][j * 2 + 1];
                if (bias) { v0 += bias[c]; v1 += bias[c + 1]; }
                if (act == 1) {
                    v0 = v0 >= 0.f ? v0 : 0.01f * v0;
                    v1 = v1 >= 0.f ? v1 : 0.01f * v1;
                }
                *(float2*)(C + (size_t)r * N + c) = make_float2(v0, v1);
            }
        }
    }
}

// ------------------- fused edge logits (ep composed on the fly) -------------------
// one warp per edge (grid-stride); lane l owns channel c = 32h + l for each head h
__global__ __launch_bounds__(256, 2) void k_logits(const float* __restrict__ P,
                                                   const float* __restrict__ q,
                                                   const float* __restrict__ att) {
    const int lane = threadIdx.x & 31;
    const int wid = threadIdx.x >> 5;
    const int wpb = blockDim.x >> 5;

    // per-lane constants held in registers
    float Pr[EDGE_IN][HEADS], qr[HEADS], ar[HEADS];
#pragma unroll
    for (int h = 0; h < HEADS; h++) {
        int c = h * 32 + lane;
        qr[h] = q[c];
        ar[h] = att[c];
#pragma unroll
        for (int k = 0; k < EDGE_IN; k++) Pr[k][h] = P[k * HID + c];
    }

    for (int e = blockIdx.x * wpb + wid; e < E_EDGES; e += gridDim.x * wpb) {
        int s = g_src[e];
        int d = g_dst[e];
        const float* ap = g_attrS + (size_t)e * EDGE_IN;
        float attr[EDGE_IN];
#pragma unroll
        for (int k = 0; k < EDGE_IN; k++) attr[k] = __ldg(ap + k);
        const float* xls = g_xl + (size_t)s * HID;
        const float* xrd = g_xr + (size_t)d * HID;
        float lg[HEADS];
#pragma unroll
        for (int h = 0; h < HEADS; h++) {
            int c = h * 32 + lane;
            float ep = qr[h];
#pragma unroll
            for (int k = 0; k < EDGE_IN; k++) ep = fmaf(attr[k], Pr[k][h], ep);
            float m = xls[c] + xrd[c] + ep;
            m = m >= 0.f ? m : 0.2f * m;
            lg[h] = m * ar[h];
        }
#pragma unroll
        for (int h = 0; h < HEADS; h++)
#pragma unroll
            for (int off = 16; off; off >>= 1)
                lg[h] += __shfl_xor_sync(0xffffffffu, lg[h], off);
        if (lane == 0) {
#pragma unroll
            for (int h = 0; h < HEADS; h++) g_logits[(size_t)e * HEADS + h] = lg[h];
        }
    }
}

// ------------------- per-node softmax stats (max, sum-exp) ------------
__global__ void k_softmax() {
    int node = (blockIdx.x * blockDim.x + threadIdx.x) >> 5;
    int lane = threadIdx.x & 31;
    if (node >= N_NODES) return;
    int s0 = g_rowptr[node], s1 = g_rowptr[node + 1];
    float mh[HEADS];
#pragma unroll
    for (int h = 0; h < HEADS; h++) mh[h] = -1e30f;
    for (int i = s0 + lane; i < s1; i += 32) {
        const float* Lp = g_logits + (size_t)i * HEADS;
#pragma unroll
        for (int h = 0; h < HEADS; h++) mh[h] = fmaxf(mh[h], Lp[h]);
    }
#pragma unroll
    for (int h = 0; h < HEADS; h++)
#pragma unroll
        for (int off = 16; off; off >>= 1)
            mh[h] = fmaxf(mh[h], __shfl_xor_sync(0xffffffffu, mh[h], off));
    float sh[HEADS];
#pragma unroll
    for (int h = 0; h < HEADS; h++) sh[h] = 0.f;
    for (int i = s0 + lane; i < s1; i += 32) {
        const float* Lp = g_logits + (size_t)i * HEADS;
#pragma unroll
        for (int h = 0; h < HEADS; h++) sh[h] += expf(Lp[h] - mh[h]);
    }
#pragma unroll
    for (int h = 0; h < HEADS; h++)
#pragma unroll
        for (int off = 16; off; off >>= 1) sh[h] += __shfl_xor_sync(0xffffffffu, sh[h], off);
    if (lane == 0) {
#pragma unroll
        for (int h = 0; h < HEADS; h++) {
            g_mx[node * HEADS + h] = mh[h];
            g_den[node * HEADS + h] = sh[h];
        }
    }
}

// ------------------- per-node aggregation + BN + leaky + residual ------------
__global__ __launch_bounds__(256) void k_agg(const float* __restrict__ conv_b,
                                             const float* __restrict__ bn_g,
                                             const float* __restrict__ bn_b,
                                             const float* __restrict__ bn_rm,
                                             const float* __restrict__ bn_rv,
                                             int layer) {
    int n = blockIdx.x;
    int t = threadIdx.x;
    int head = t >> 5;
    __shared__ float smx[HEADS], sden[HEADS];
    __shared__ float sal[64 * HEADS];
    __shared__ int ssrc[64];
    if (t < HEADS) {
        smx[t] = g_mx[n * HEADS + t];
        sden[t] = g_den[n * HEADS + t] + 1e-16f;
    }
    int s0 = g_rowptr[n], s1 = g_rowptr[n + 1];
    float acc = 0.f;
    for (int c0 = s0; c0 < s1; c0 += 64) {
        int cnt = min(64, s1 - c0);
        __syncthreads();
        for (int idx = t; idx < cnt * HEADS; idx += 256) {
            int i = idx >> 3, h = idx & 7;
            sal[idx] = expf(g_logits[(size_t)(c0 + i) * HEADS + h] - smx[h]) / sden[h];
        }
        for (int idx = t; idx < cnt; idx += 256) ssrc[idx] = g_src[c0 + idx];
        __syncthreads();
        for (int i = 0; i < cnt; i++)
            acc += sal[i * HEADS + head] * g_xl[(size_t)ssrc[i] * HID + t];
    }
    float v = acc + conv_b[t];
    v = (v - bn_rm[t]) * rsqrtf(bn_rv[t] + 1e-5f) * bn_g[t] + bn_b[t];
    v = v >= 0.f ? v : 0.01f * v;
    if (layer >= 1) v += g_h[(size_t)n * HID + t];
    g_h[(size_t)n * HID + t] = v;
}

// ------------------- output head: out = h2 @ W2 + b2 -------------------
__global__ void k_out(const float* __restrict__ W2, const float* __restrict__ b2,
                      float* __restrict__ out) {
    int n = (blockIdx.x * blockDim.x + threadIdx.x) >> 5;
    int lane = threadIdx.x & 31;
    if (n >= N_NODES) return;
    const float* hr = g_h2 + (size_t)n * 128;
    float a = 0.f;
#pragma unroll
    for (int j = 0; j < 4; j++) a += hr[j * 32 + lane] * W2[j * 32 + lane];
#pragma unroll
    for (int off = 16; off; off >>= 1) a += __shfl_xor_sync(0xffffffffu, a, off);
    if (lane == 0) out[n] = a + b2[0];
}

// ------------------- launcher -------------------
extern "C" void kernel_launch(void* const* d_in, const int* in_sizes, int n_in,
                              void* d_out, int out_size) {
    const float* x        = (const float*)d_in[0];
    const int*   ei       = (const int*)d_in[1];
    const float* eattr    = (const float*)d_in[2];
    const float* node_W   = (const float*)d_in[3];
    const float* node_b   = (const float*)d_in[4];
    const float* edge_W   = (const float*)d_in[5];
    const float* edge_b   = (const float*)d_in[6];
    const float* Wl       = (const float*)d_in[7];
    const float* bl       = (const float*)d_in[8];
    const float* Wr       = (const float*)d_in[9];
    const float* br       = (const float*)d_in[10];
    const float* We       = (const float*)d_in[11];
    const float* att      = (const float*)d_in[12];
    const float* conv_b   = (const float*)d_in[13];
    const float* Weu      = (const float*)d_in[14];
    const float* beu      = (const float*)d_in[15];
    const float* bn_g     = (const float*)d_in[16];
    const float* bn_b     = (const float*)d_in[17];
    const float* bn_rm    = (const float*)d_in[18];
    const float* bn_rv    = (const float*)d_in[19];
    const float* out_W1   = (const float*)d_in[20];
    const float* out_b1   = (const float*)d_in[21];
    const float* out_W2   = (const float*)d_in[22];
    const float* out_b2   = (const float*)d_in[23];
    float* out = (float*)d_out;

    const int* src = ei;
    const int* dst = ei + E_EDGES;

    float *hPtr, *xlPtr, *xrPtr, *h2Ptr, *Pp, *qp;
    cudaGetSymbolAddress((void**)&hPtr, g_h);
    cudaGetSymbolAddress((void**)&xlPtr, g_xl);
    cudaGetSymbolAddress((void**)&xrPtr, g_xr);
    cudaGetSymbolAddress((void**)&h2Ptr, g_h2);
    cudaGetSymbolAddress((void**)&Pp, g_P);
    cudaGetSymbolAddress((void**)&qp, g_q);

    // CSR build
    k_zero_fill<<<cdiv(N_NODES, 256), 256>>>();
    k_count<<<cdiv(E_EDGES, 256), 256>>>(dst);
    k_scan<<<1, 1024>>>();
    k_scatter<<<cdiv(E_EDGES, 256), 256>>>(src, dst);
    k_permattr<<<cdiv(E_EDGES * EDGE_IN, 256), 256>>>(eattr);

    // node input projection
    k_hinit<<<N_NODES, HID>>>(x, node_W, node_b);

    // fp32-exact composition of the linear edge chain
    k_initM<<<1, HID>>>(edge_W, edge_b);
    for (int i = 0; i < L_LAYERS; i++)
        k_compose<<<1, HID>>>(We + (size_t)i * HID * HID, Weu + (size_t)i * HID * HID,
                              beu + i * HID, i, i & 1, i < L_LAYERS - 1 ? 1 : 0);

    for (int i = 0; i < L_LAYERS; i++) {
        const float* Wl_i = Wl + (size_t)i * HID * HID;
        const float* Wr_i = Wr + (size_t)i * HID * HID;

        dim3 gN(cdiv(HID, 128), cdiv(N_NODES, 128));

        k_mma<<<gN, 256>>>(hPtr, Wl_i, bl + i * HID, xlPtr, N_NODES, HID, HID, 0);
        k_mma<<<gN, 256>>>(hPtr, Wr_i, br + i * HID, xrPtr, N_NODES, HID, HID, 0);

        k_logits<<<1184, 256>>>(Pp + (size_t)i * EDGE_IN * HID, qp + (size_t)i * HID,
                                att + (size_t)i * HEADS * OUTC);
        k_softmax<<<cdiv(N_NODES * 32, 256), 256>>>();
        k_agg<<<N_NODES, 256>>>(conv_b + i * HID, bn_g + i * HID, bn_b + i * HID,
                                bn_rm + i * HID, bn_rv + i * HID, i);
    }

    // output MLP
    dim3 gO(1, cdiv(N_NODES, 128));
    k_mma<<<gO, 256>>>(hPtr, out_W1, out_b1, h2Ptr, N_NODES, HID / 2, HID, 1);
    k_out<<<cdiv(N_NODES * 32, 256), 256>>>(out_W2, out_b2, out);
}